// round 3
// baseline (speedup 1.0000x reference)
#include <cuda_runtime.h>
#include <math.h>

// Problem: B=4, T=2048, D=2048, HEADS=16
//   kv  = x(8192x2048) @ w_qk^T(2048x4096)          -> g_kv (8192x4096)
//   s[b,i,j] = scale * sum_m k0[b,m,i]*v[b,j,m]     -> g_s  (4x2048x2048)
//   a = softmax_j(s)                                 (in place)
//   q[b,i,d] = sum_t a[b,i,t]*v[b,t,d]              -> g_q
//   out[r,:] = q[b, h*128+vh, :] @ w_dense^T + b    (r = vh*64 + b*16 + h)

#define BM 128
#define BN 128
#define BK 16

static __device__ float g_kv[33554432];   // 4*2048*4096  (k0 | v interleaved per row)
static __device__ float g_s [16777216];   // 4*2048*2048
static __device__ float g_q [16777216];   // 4*2048*2048

__device__ __forceinline__ size_t gather_row_off(int r) {
    // out row r = vh*64 + b*16 + h  -> source q[b, h*128 + vh, :]
    int vh = r >> 6;
    int b  = (r >> 4) & 3;
    int h  = r & 15;
    return ((size_t)b * 2048 + (size_t)h * 128 + (size_t)vh) * 2048;
}

// C(m,n) = alpha * sum_k A(m,k)*B(n,k) [+ bias(n)]
// A_KMAJOR: A(m,k) = A[rowoff(m) + k]   (K contiguous; smem-transposed load)
//   else  : A(m,k) = A[k*lda + m]       (M contiguous; direct load)
// B_KMAJOR: B(n,k) = B[n*ldb + k]  else B(n,k) = B[k*ldb + n]
template<bool A_KMAJOR, bool B_KMAJOR, bool GATHER_A, bool ADD_BIAS>
__global__ __launch_bounds__(256)
void gemm128(const float* __restrict__ A, int lda, long strideA,
             const float* __restrict__ B, int ldb, long strideB,
             float* __restrict__ C, int ldc, long strideC,
             int Ksize, float alpha, const float* __restrict__ bias)
{
    __shared__ float As[BK][BM + 4];
    __shared__ float Bs[BK][BN + 4];

    A += (size_t)blockIdx.z * strideA;
    B += (size_t)blockIdx.z * strideB;
    C += (size_t)blockIdx.z * strideC;

    const int tid = threadIdx.x;
    const int tx = tid & 15;          // 0..15 -> N
    const int ty = tid >> 4;          // 0..15 -> M
    const int m0 = blockIdx.y * BM;
    const int n0 = blockIdx.x * BN;

    float acc[8][8];
#pragma unroll
    for (int i = 0; i < 8; i++)
#pragma unroll
        for (int j = 0; j < 8; j++) acc[i][j] = 0.f;

    for (int k0 = 0; k0 < Ksize; k0 += BK) {
        // ---- load A tile ----
        if (A_KMAJOR) {
#pragma unroll
            for (int l = 0; l < 2; l++) {
                int idx = tid + l * 256;          // 0..511
                int row = idx >> 2;               // 0..127
                int kc  = (idx & 3) * 4;          // 0,4,8,12
                size_t roff = GATHER_A ? gather_row_off(m0 + row)
                                       : (size_t)(m0 + row) * (size_t)lda;
                float4 v = *(const float4*)(A + roff + k0 + kc);
                As[kc + 0][row] = v.x;
                As[kc + 1][row] = v.y;
                As[kc + 2][row] = v.z;
                As[kc + 3][row] = v.w;
            }
        } else {
#pragma unroll
            for (int l = 0; l < 2; l++) {
                int idx = tid + l * 256;
                int kk  = idx >> 5;               // 0..15
                int c   = (idx & 31) * 4;         // 0..124
                float4 v = *(const float4*)(A + (size_t)(k0 + kk) * (size_t)lda + m0 + c);
                *(float4*)&As[kk][c] = v;
            }
        }
        // ---- load B tile ----
        if (B_KMAJOR) {
#pragma unroll
            for (int l = 0; l < 2; l++) {
                int idx = tid + l * 256;
                int row = idx >> 2;               // 0..127 (n)
                int kc  = (idx & 3) * 4;
                float4 v = *(const float4*)(B + (size_t)(n0 + row) * (size_t)ldb + k0 + kc);
                Bs[kc + 0][row] = v.x;
                Bs[kc + 1][row] = v.y;
                Bs[kc + 2][row] = v.z;
                Bs[kc + 3][row] = v.w;
            }
        } else {
#pragma unroll
            for (int l = 0; l < 2; l++) {
                int idx = tid + l * 256;
                int kk  = idx >> 5;
                int c   = (idx & 31) * 4;
                float4 v = *(const float4*)(B + (size_t)(k0 + kk) * (size_t)ldb + n0 + c);
                *(float4*)&Bs[kk][c] = v;
            }
        }
        __syncthreads();

#pragma unroll
        for (int kk = 0; kk < BK; kk++) {
            float a_frag[8], b_frag[8];
            *(float4*)&a_frag[0] = *(const float4*)&As[kk][ty * 4];
            *(float4*)&a_frag[4] = *(const float4*)&As[kk][64 + ty * 4];
            *(float4*)&b_frag[0] = *(const float4*)&Bs[kk][tx * 4];
            *(float4*)&b_frag[4] = *(const float4*)&Bs[kk][64 + tx * 4];
#pragma unroll
            for (int i = 0; i < 8; i++)
#pragma unroll
                for (int j = 0; j < 8; j++)
                    acc[i][j] += a_frag[i] * b_frag[j];
        }
        __syncthreads();
    }

    // ---- epilogue ----
#pragma unroll
    for (int i = 0; i < 8; i++) {
        int m = m0 + (i < 4 ? ty * 4 + i : 64 + ty * 4 + (i - 4));
#pragma unroll
        for (int jh = 0; jh < 2; jh++) {
            int n = n0 + jh * 64 + tx * 4;
            float4 r;
            r.x = alpha * acc[i][jh * 4 + 0];
            r.y = alpha * acc[i][jh * 4 + 1];
            r.z = alpha * acc[i][jh * 4 + 2];
            r.w = alpha * acc[i][jh * 4 + 3];
            if (ADD_BIAS) {
                r.x += bias[n + 0];
                r.y += bias[n + 1];
                r.z += bias[n + 2];
                r.w += bias[n + 3];
            }
            *(float4*)&C[(size_t)m * (size_t)ldc + n] = r;
        }
    }
}

// Row softmax, ncols = 2048, 256 threads, 8 elems/thread.
__global__ __launch_bounds__(256)
void softmax2048(float* __restrict__ data)
{
    float* p = data + (size_t)blockIdx.x * 2048;
    int tid = threadIdx.x;
    int warp = tid >> 5, lane = tid & 31;
    __shared__ float red[8];

    float4 v0 = *(float4*)(p + tid * 4);
    float4 v1 = *(float4*)(p + 1024 + tid * 4);

    float m = fmaxf(fmaxf(fmaxf(v0.x, v0.y), fmaxf(v0.z, v0.w)),
                    fmaxf(fmaxf(v1.x, v1.y), fmaxf(v1.z, v1.w)));
#pragma unroll
    for (int o = 16; o > 0; o >>= 1) m = fmaxf(m, __shfl_xor_sync(0xffffffffu, m, o));
    if (lane == 0) red[warp] = m;
    __syncthreads();
    float bm = red[0];
#pragma unroll
    for (int i = 1; i < 8; i++) bm = fmaxf(bm, red[i]);
    __syncthreads();

    v0.x = __expf(v0.x - bm); v0.y = __expf(v0.y - bm);
    v0.z = __expf(v0.z - bm); v0.w = __expf(v0.w - bm);
    v1.x = __expf(v1.x - bm); v1.y = __expf(v1.y - bm);
    v1.z = __expf(v1.z - bm); v1.w = __expf(v1.w - bm);

    float s = v0.x + v0.y + v0.z + v0.w + v1.x + v1.y + v1.z + v1.w;
#pragma unroll
    for (int o = 16; o > 0; o >>= 1) s += __shfl_xor_sync(0xffffffffu, s, o);
    if (lane == 0) red[warp] = s;
    __syncthreads();
    float tot = red[0];
#pragma unroll
    for (int i = 1; i < 8; i++) tot += red[i];

    float inv = 1.f / tot;
    v0.x *= inv; v0.y *= inv; v0.z *= inv; v0.w *= inv;
    v1.x *= inv; v1.y *= inv; v1.z *= inv; v1.w *= inv;
    *(float4*)(p + tid * 4) = v0;
    *(float4*)(p + 1024 + tid * 4) = v1;
}

extern "C" void kernel_launch(void* const* d_in, const int* in_sizes, int n_in,
                              void* d_out, int out_size)
{
    const float* x       = (const float*)d_in[0];   // (4,2048,2048)
    const float* w_qk    = (const float*)d_in[1];   // (4096,2048)
    const float* w_dense = (const float*)d_in[2];   // (2048,2048)
    const float* b_dense = (const float*)d_in[3];   // (2048,)
    float* out = (float*)d_out;                     // (4,2048,2048)

    float *kv, *s, *q;
    cudaGetSymbolAddress((void**)&kv, g_kv);
    cudaGetSymbolAddress((void**)&s,  g_s);
    cudaGetSymbolAddress((void**)&q,  g_q);

    const float scale = (float)(1.0 / sqrt(2048.0 * 2047.0 / 2.0));
    const long sKV = 2048L * 4096L;   // per-batch kv stride
    const long sSQ = 2048L * 2048L;   // per-batch s/q stride

    // K1: kv = x @ w_qk^T   (M=8192, N=4096, K=2048), both K-major
    {
        dim3 g(4096 / BN, 8192 / BM, 1);
        gemm128<true, true, false, false><<<g, 256>>>(
            x, 2048, 0, w_qk, 2048, 0, kv, 4096, 0, 2048, 1.f, nullptr);
    }

    // K2: s[b](i,j) = scale * sum_m k0[b](m,i) * v[b](j,m)
    //   A = k0 base (M-contiguous, lda=4096), B = v base (K-contiguous, ldb=4096)
    {
        dim3 g(2048 / BN, 2048 / BM, 4);
        gemm128<false, true, false, false><<<g, 256>>>(
            kv, 4096, sKV, kv + 2048, 4096, sKV, s, 2048, sSQ, 2048, scale, nullptr);
    }

    // K3: softmax over last axis, 4*2048 rows
    softmax2048<<<8192, 256>>>(s);

    // K4: q[b] = a[b] @ v[b]   (A K-major, B N-contiguous ldb=4096)
    {
        dim3 g(2048 / BN, 2048 / BM, 4);
        gemm128<true, false, false, false><<<g, 256>>>(
            s, 2048, sSQ, kv + 2048, 4096, sKV, q, 2048, sSQ, 2048, 1.f, nullptr);
    }

    // K5: out = gather(q) @ w_dense^T + b_dense  (M=8192, N=2048, K=2048)
    {
        dim3 g(2048 / BN, 8192 / BM, 1);
        gemm128<true, true, true, true><<<g, 256>>>(
            q, 2048, 0, w_dense, 2048, 0, out, 2048, 0, 2048, 1.f, b_dense);
    }
}

// round 5
// speedup vs baseline: 2.0963x; 2.0963x over previous
#include <cuda_runtime.h>
#include <cuda_bf16.h>
#include <math.h>
#include <stdint.h>

// Problem: B=4, T=2048, D=2048, HEADS=16
// Chain:
//   K1: kv = x(8192x2048) @ w_qk^T(4096x2048)      -> g_kv fp32
//   prep: kt=k0^T, v, vt=v^T  (bf16 hi/lo splits, K-major rows of 2048)
//   K2: s[b,i,j] = scale * kt[i,:] . v[j,:]        -> g_s fp32
//   K3: row softmax of s -> bf16 hi/lo splits (a)
//   K4: q = a @ vt^T                                -> g_q fp32
//   prep: qg[r] = q[gather(r)] bf16 splits
//   K5: out = qg @ w_dense^T + bias
//
// GEMM engine: mma.sync.aligned.m16n8k16 bf16 (plain sm_103 target: tcgen05
// is 'a'-suffix-gated and unavailable in this toolchain path). 2-way bf16
// split of both operands, 3 HMMA products (hh, hl, lh) per k-step.

// ---------------------------------------------------------------- scratch ---
static __device__ float g_kv[33554432];   // 4*2048*4096
static __device__ float g_s [16777216];   // 4*2048*2048
static __device__ float g_q [16777216];   // 4*2048*2048

static __device__ __nv_bfloat16 g_xh[16777216],  g_xl[16777216];
static __device__ __nv_bfloat16 g_wqh[8388608],  g_wql[8388608];
static __device__ __nv_bfloat16 g_wdh[4194304],  g_wdl[4194304];
static __device__ __nv_bfloat16 g_kth[16777216], g_ktl[16777216];
static __device__ __nv_bfloat16 g_vh [16777216], g_vl [16777216];
static __device__ __nv_bfloat16 g_vth[16777216], g_vtl[16777216];
static __device__ __nv_bfloat16 g_ah [16777216], g_al [16777216];
static __device__ __nv_bfloat16 g_qgh[16777216], g_qgl[16777216];

// --------------------------------------------------------------- helpers ---
__device__ __forceinline__ uint32_t smem_u32(const void* p) {
    uint32_t a;
    asm("{ .reg .u64 t; cvta.to.shared.u64 t, %1; cvt.u32.u64 %0, t; }"
        : "=r"(a) : "l"(p));
    return a;
}
__device__ __forceinline__ void cp16(uint32_t dst, const void* src) {
    asm volatile("cp.async.cg.shared.global [%0], [%1], 16;"
                 :: "r"(dst), "l"(src) : "memory");
}
#define CP_COMMIT() asm volatile("cp.async.commit_group;" ::: "memory")
#define CP_WAIT1()  asm volatile("cp.async.wait_group 1;" ::: "memory")

__device__ __forceinline__ void ldsm4(uint32_t* r, uint32_t addr) {
    asm volatile("ldmatrix.sync.aligned.m8n8.x4.shared.b16 {%0,%1,%2,%3}, [%4];"
                 : "=r"(r[0]), "=r"(r[1]), "=r"(r[2]), "=r"(r[3]) : "r"(addr));
}
__device__ __forceinline__ void mma16816(float* c, const uint32_t* a, const uint32_t* b) {
    asm volatile(
        "mma.sync.aligned.m16n8k16.row.col.f32.bf16.bf16.f32 "
        "{%0,%1,%2,%3}, {%4,%5,%6,%7}, {%8,%9}, {%0,%1,%2,%3};"
        : "+f"(c[0]), "+f"(c[1]), "+f"(c[2]), "+f"(c[3])
        : "r"(a[0]), "r"(a[1]), "r"(a[2]), "r"(a[3]), "r"(b[0]), "r"(b[1]));
}

__device__ __forceinline__ void split1(float x, __nv_bfloat16& h, __nv_bfloat16& l) {
    h = __float2bfloat16(x);
    l = __float2bfloat16(x - __bfloat162float(h));
}
__device__ __forceinline__ size_t gather_row_off(int r) {
    int vh = r >> 6;
    int b  = (r >> 4) & 3;
    int h  = r & 15;
    return ((size_t)b * 2048 + (size_t)h * 128 + (size_t)vh) * 2048;
}

// ------------------------------------------------------------ bf16 GEMM ----
// C(m,n) = alpha*sum_k (Ah+Al)(m,k)*(Bh+Bl)(n,k) [+bias(n)], drop Al*Bl.
// All operands K-major bf16 with row length 2048. K=2048.
// Block 128x128xBK32, 256 thr (8 warps, 2x4), warp tile 64x32, 3-stage cp.async.
#define GK       2048
#define GBK      32
#define NCHUNK   (GK / GBK)        // 64
#define ROWB     80u               // padded row bytes (32 bf16 = 64B data + 16B pad)
#define TILE_B   (128u * ROWB)     // 10240
#define OFF_AH   0u
#define OFF_AL   TILE_B
#define OFF_BH   (2u * TILE_B)
#define OFF_BL   (3u * TILE_B)
#define STAGE_B  (4u * TILE_B)     // 40960
#define GEMM_SMEM (3u * STAGE_B)   // 122880

__global__ __launch_bounds__(256, 1)
void gemm_mma(const __nv_bfloat16* __restrict__ Ah, const __nv_bfloat16* __restrict__ Al,
              size_t strideA,
              const __nv_bfloat16* __restrict__ Bh, const __nv_bfloat16* __restrict__ Bl,
              size_t strideB,
              float* __restrict__ C, int ldc, size_t strideC,
              float alpha, const float* __restrict__ bias)
{
    extern __shared__ char smem[];
    const uint32_t sbase = smem_u32(smem);

    const int tid  = threadIdx.x;
    const int lane = tid & 31;
    const int wid  = tid >> 5;
    const int wm0  = (wid & 1) * 64;    // warp M offset in tile
    const int wn0  = (wid >> 1) * 32;   // warp N offset in tile

    Ah += blockIdx.z * strideA;  Al += blockIdx.z * strideA;
    Bh += blockIdx.z * strideB;  Bl += blockIdx.z * strideB;
    C  += blockIdx.z * strideC;
    const int m0 = blockIdx.y * 128;
    const int n0 = blockIdx.x * 128;

    // loader indices: thread -> (row r, r+64) x chunk c for each of 4 tiles
    const int lc = tid & 3;         // 16B chunk 0..3
    const int lr = tid >> 2;        // row 0..63

    auto load_stage = [&](int t) {
        const uint32_t sb = sbase + (uint32_t)(t % 3) * STAGE_B;
        const int ks = t * GBK;
        const size_t soff0 = (size_t)(m0 + lr) * GK + ks + lc * 8;
        const size_t soff1 = (size_t)(m0 + lr + 64) * GK + ks + lc * 8;
        const size_t toff0 = (size_t)(n0 + lr) * GK + ks + lc * 8;
        const size_t toff1 = (size_t)(n0 + lr + 64) * GK + ks + lc * 8;
        const uint32_t d0 = (uint32_t)lr * ROWB + lc * 16;
        const uint32_t d1 = (uint32_t)(lr + 64) * ROWB + lc * 16;
        cp16(sb + OFF_AH + d0, Ah + soff0);
        cp16(sb + OFF_AH + d1, Ah + soff1);
        cp16(sb + OFF_AL + d0, Al + soff0);
        cp16(sb + OFF_AL + d1, Al + soff1);
        cp16(sb + OFF_BH + d0, Bh + toff0);
        cp16(sb + OFF_BH + d1, Bh + toff1);
        cp16(sb + OFF_BL + d0, Bl + toff0);
        cp16(sb + OFF_BL + d1, Bl + toff1);
    };

    float acc[4][4][4];
#pragma unroll
    for (int i = 0; i < 4; i++)
#pragma unroll
        for (int j = 0; j < 4; j++)
#pragma unroll
            for (int k = 0; k < 4; k++) acc[i][j][k] = 0.f;

    // ldmatrix lane-base offsets (within a stage)
    //  A: lanes 0-15 rows wm0+0..15 (k0-7), lanes 16-31 same rows k8-15
    const uint32_t a_lbase = (uint32_t)(wm0 + (lane & 15)) * ROWB + (uint32_t)(lane >> 4) * 16;
    //  B: tiles (n0-7,k0-7)(n0-7,k8-15)(n8-15,k0-7)(n8-15,k8-15)
    const uint32_t b_lbase = (uint32_t)(wn0 + ((lane >> 4) & 1) * 8 + (lane & 7)) * ROWB
                           + (uint32_t)((lane >> 3) & 1) * 16;

    load_stage(0); CP_COMMIT();
    load_stage(1); CP_COMMIT();

    for (int t = 0; t < NCHUNK; t++) {
        CP_WAIT1();
        __syncthreads();
        if (t + 2 < NCHUNK) load_stage(t + 2);
        CP_COMMIT();

        const uint32_t sb = sbase + (uint32_t)(t % 3) * STAGE_B;
#pragma unroll
        for (int k16 = 0; k16 < 2; k16++) {
            const uint32_t kb = (uint32_t)k16 * 32;   // 16 bf16 = 32 bytes
            uint32_t ah[4][4], al[4][4], bh[2][4], bl[2][4];
#pragma unroll
            for (int mt = 0; mt < 4; mt++) {
                ldsm4(ah[mt], sb + OFF_AH + a_lbase + (uint32_t)mt * (16u * ROWB) + kb);
                ldsm4(al[mt], sb + OFF_AL + a_lbase + (uint32_t)mt * (16u * ROWB) + kb);
            }
#pragma unroll
            for (int p = 0; p < 2; p++) {
                ldsm4(bh[p], sb + OFF_BH + b_lbase + (uint32_t)p * (16u * ROWB) + kb);
                ldsm4(bl[p], sb + OFF_BL + b_lbase + (uint32_t)p * (16u * ROWB) + kb);
            }
#pragma unroll
            for (int mt = 0; mt < 4; mt++) {
#pragma unroll
                for (int p = 0; p < 2; p++) {
                    mma16816(acc[mt][2 * p + 0], ah[mt], &bh[p][0]);
                    mma16816(acc[mt][2 * p + 1], ah[mt], &bh[p][2]);
                    mma16816(acc[mt][2 * p + 0], ah[mt], &bl[p][0]);
                    mma16816(acc[mt][2 * p + 1], ah[mt], &bl[p][2]);
                    mma16816(acc[mt][2 * p + 0], al[mt], &bh[p][0]);
                    mma16816(acc[mt][2 * p + 1], al[mt], &bh[p][2]);
                }
            }
        }
        __syncthreads();
    }

    // ---- epilogue: direct fp32 stores ----
    const int er = lane >> 2;          // row group 0..7
    const int ec = (lane & 3) * 2;     // col pair
#pragma unroll
    for (int mt = 0; mt < 4; mt++) {
#pragma unroll
        for (int nt = 0; nt < 4; nt++) {
            int m = m0 + wm0 + mt * 16 + er;
            int n = n0 + wn0 + nt * 8 + ec;
            float b0 = 0.f, b1 = 0.f;
            if (bias) { b0 = __ldg(bias + n); b1 = __ldg(bias + n + 1); }
            float2 v0, v1;
            v0.x = alpha * acc[mt][nt][0] + b0;
            v0.y = alpha * acc[mt][nt][1] + b1;
            v1.x = alpha * acc[mt][nt][2] + b0;
            v1.y = alpha * acc[mt][nt][3] + b1;
            *(float2*)&C[(size_t)m * (size_t)ldc + n]       = v0;
            *(float2*)&C[(size_t)(m + 8) * (size_t)ldc + n] = v1;
        }
    }
}

// ----------------------------------------------------------- prep kernels ---
__global__ __launch_bounds__(256)
void copy_split_k(const float* __restrict__ src, size_t src_rstride, size_t src_bstride,
                  __nv_bfloat16* __restrict__ dh, __nv_bfloat16* __restrict__ dl,
                  size_t dst_bstride)
{
    size_t row = blockIdx.y;
    size_t col = (size_t)blockIdx.x * 1024 + threadIdx.x * 4;
    float4 v = *(const float4*)(src + (size_t)blockIdx.z * src_bstride + row * src_rstride + col);
    __nv_bfloat16 h0, h1, h2, h3, l0, l1, l2, l3;
    split1(v.x, h0, l0); split1(v.y, h1, l1);
    split1(v.z, h2, l2); split1(v.w, h3, l3);
    size_t o = (size_t)blockIdx.z * dst_bstride + row * 2048 + col;
    ((__nv_bfloat162*)(dh + o))[0] = __halves2bfloat162(h0, h1);
    ((__nv_bfloat162*)(dh + o))[1] = __halves2bfloat162(h2, h3);
    ((__nv_bfloat162*)(dl + o))[0] = __halves2bfloat162(l0, l1);
    ((__nv_bfloat162*)(dl + o))[1] = __halves2bfloat162(l2, l3);
}

__global__ __launch_bounds__(256)
void transpose_split_k(const float* __restrict__ src, size_t src_bstride, int src_ld,
                       __nv_bfloat16* __restrict__ dh, __nv_bfloat16* __restrict__ dl,
                       size_t dst_bstride)
{
    __shared__ float tile[32][33];
    int tx = threadIdx.x, ty = threadIdx.y;      // blockDim (32, 8)
    int i0 = blockIdx.x * 32, m0 = blockIdx.y * 32;
    const float* s = src + (size_t)blockIdx.z * src_bstride;
#pragma unroll
    for (int r = 0; r < 4; r++)
        tile[ty + r * 8][tx] = s[(size_t)(m0 + ty + r * 8) * src_ld + i0 + tx];
    __syncthreads();
#pragma unroll
    for (int r = 0; r < 4; r++) {
        float x = tile[tx][ty + r * 8];
        __nv_bfloat16 h, l; split1(x, h, l);
        size_t o = (size_t)blockIdx.z * dst_bstride +
                   (size_t)(i0 + ty + r * 8) * 2048 + m0 + tx;
        dh[o] = h; dl[o] = l;
    }
}

__global__ __launch_bounds__(256)
void softmax_split_k(const float* __restrict__ s,
                     __nv_bfloat16* __restrict__ ah, __nv_bfloat16* __restrict__ al)
{
    const float* p = s + (size_t)blockIdx.x * 2048;
    int tid = threadIdx.x, warp = tid >> 5, lane = tid & 31;
    __shared__ float red[8];

    float4 v0 = *(const float4*)(p + tid * 4);
    float4 v1 = *(const float4*)(p + 1024 + tid * 4);

    float m = fmaxf(fmaxf(fmaxf(v0.x, v0.y), fmaxf(v0.z, v0.w)),
                    fmaxf(fmaxf(v1.x, v1.y), fmaxf(v1.z, v1.w)));
#pragma unroll
    for (int o = 16; o > 0; o >>= 1) m = fmaxf(m, __shfl_xor_sync(0xffffffffu, m, o));
    if (lane == 0) red[warp] = m;
    __syncthreads();
    float bm = red[0];
#pragma unroll
    for (int i = 1; i < 8; i++) bm = fmaxf(bm, red[i]);
    __syncthreads();

    v0.x = __expf(v0.x - bm); v0.y = __expf(v0.y - bm);
    v0.z = __expf(v0.z - bm); v0.w = __expf(v0.w - bm);
    v1.x = __expf(v1.x - bm); v1.y = __expf(v1.y - bm);
    v1.z = __expf(v1.z - bm); v1.w = __expf(v1.w - bm);

    float sm = v0.x + v0.y + v0.z + v0.w + v1.x + v1.y + v1.z + v1.w;
#pragma unroll
    for (int o = 16; o > 0; o >>= 1) sm += __shfl_xor_sync(0xffffffffu, sm, o);
    if (lane == 0) red[warp] = sm;
    __syncthreads();
    float tot = red[0];
#pragma unroll
    for (int i = 1; i < 8; i++) tot += red[i];
    float inv = 1.f / tot;

    size_t base = (size_t)blockIdx.x * 2048;
    float vals[8] = {v0.x * inv, v0.y * inv, v0.z * inv, v0.w * inv,
                     v1.x * inv, v1.y * inv, v1.z * inv, v1.w * inv};
    size_t offs[2] = {base + tid * 4, base + 1024 + tid * 4};
#pragma unroll
    for (int half = 0; half < 2; half++) {
        __nv_bfloat16 h0, h1, h2, h3, l0, l1, l2, l3;
        split1(vals[half * 4 + 0], h0, l0); split1(vals[half * 4 + 1], h1, l1);
        split1(vals[half * 4 + 2], h2, l2); split1(vals[half * 4 + 3], h3, l3);
        size_t o = offs[half];
        ((__nv_bfloat162*)(ah + o))[0] = __halves2bfloat162(h0, h1);
        ((__nv_bfloat162*)(ah + o))[1] = __halves2bfloat162(h2, h3);
        ((__nv_bfloat162*)(al + o))[0] = __halves2bfloat162(l0, l1);
        ((__nv_bfloat162*)(al + o))[1] = __halves2bfloat162(l2, l3);
    }
}

__global__ __launch_bounds__(256)
void gather_split_k(const float* __restrict__ q,
                    __nv_bfloat16* __restrict__ dh, __nv_bfloat16* __restrict__ dl)
{
    int r = blockIdx.y;
    size_t col = (size_t)blockIdx.x * 1024 + threadIdx.x * 4;
    float4 v = *(const float4*)(q + gather_row_off(r) + col);
    __nv_bfloat16 h0, h1, h2, h3, l0, l1, l2, l3;
    split1(v.x, h0, l0); split1(v.y, h1, l1);
    split1(v.z, h2, l2); split1(v.w, h3, l3);
    size_t o = (size_t)r * 2048 + col;
    ((__nv_bfloat162*)(dh + o))[0] = __halves2bfloat162(h0, h1);
    ((__nv_bfloat162*)(dh + o))[1] = __halves2bfloat162(h2, h3);
    ((__nv_bfloat162*)(dl + o))[0] = __halves2bfloat162(l0, l1);
    ((__nv_bfloat162*)(dl + o))[1] = __halves2bfloat162(l2, l3);
}

// ------------------------------------------------------------------ driver ---
extern "C" void kernel_launch(void* const* d_in, const int* in_sizes, int n_in,
                              void* d_out, int out_size)
{
    const float* x       = (const float*)d_in[0];
    const float* w_qk    = (const float*)d_in[1];
    const float* w_dense = (const float*)d_in[2];
    const float* b_dense = (const float*)d_in[3];
    float* out = (float*)d_out;

    float *kv, *s, *q;
    cudaGetSymbolAddress((void**)&kv, g_kv);
    cudaGetSymbolAddress((void**)&s,  g_s);
    cudaGetSymbolAddress((void**)&q,  g_q);
    __nv_bfloat16 *xh, *xl, *wqh, *wql, *wdh, *wdl, *kth, *ktl, *vh, *vl,
                  *vth, *vtl, *ah, *al, *qgh, *qgl;
    cudaGetSymbolAddress((void**)&xh,  g_xh);  cudaGetSymbolAddress((void**)&xl,  g_xl);
    cudaGetSymbolAddress((void**)&wqh, g_wqh); cudaGetSymbolAddress((void**)&wql, g_wql);
    cudaGetSymbolAddress((void**)&wdh, g_wdh); cudaGetSymbolAddress((void**)&wdl, g_wdl);
    cudaGetSymbolAddress((void**)&kth, g_kth); cudaGetSymbolAddress((void**)&ktl, g_ktl);
    cudaGetSymbolAddress((void**)&vh,  g_vh);  cudaGetSymbolAddress((void**)&vl,  g_vl);
    cudaGetSymbolAddress((void**)&vth, g_vth); cudaGetSymbolAddress((void**)&vtl, g_vtl);
    cudaGetSymbolAddress((void**)&ah,  g_ah);  cudaGetSymbolAddress((void**)&al,  g_al);
    cudaGetSymbolAddress((void**)&qgh, g_qgh); cudaGetSymbolAddress((void**)&qgl, g_qgl);

    cudaFuncSetAttribute(gemm_mma, cudaFuncAttributeMaxDynamicSharedMemorySize, GEMM_SMEM);

    const float scale = (float)(1.0 / sqrt(2048.0 * 2047.0 / 2.0));
    const size_t sKV = 2048ull * 4096ull;
    const size_t sSQ = 2048ull * 2048ull;

    // splits of the raw inputs
    copy_split_k<<<dim3(2, 8192, 1), 256>>>(x,       2048, 0, xh,  xl,  0);
    copy_split_k<<<dim3(2, 4096, 1), 256>>>(w_qk,    2048, 0, wqh, wql, 0);
    copy_split_k<<<dim3(2, 2048, 1), 256>>>(w_dense, 2048, 0, wdh, wdl, 0);

    // K1: kv = x @ w_qk^T   M=8192 N=4096 K=2048
    gemm_mma<<<dim3(32, 64, 1), 256, GEMM_SMEM>>>(
        xh, xl, 0, wqh, wql, 0, kv, 4096, 0, 1.f, nullptr);

    // kv -> kt (k0^T), v (copy), vt (v^T), all bf16 splits
    transpose_split_k<<<dim3(64, 64, 4), dim3(32, 8)>>>(kv,        sKV, 4096, kth, ktl, sSQ);
    copy_split_k     <<<dim3(2, 2048, 4), 256>>>      (kv + 2048, 4096, sKV, vh,  vl,  sSQ);
    transpose_split_k<<<dim3(64, 64, 4), dim3(32, 8)>>>(kv + 2048, sKV, 4096, vth, vtl, sSQ);

    // K2: s = scale * kt @ v^T (per batch)
    gemm_mma<<<dim3(16, 16, 4), 256, GEMM_SMEM>>>(
        kth, ktl, sSQ, vh, vl, sSQ, s, 2048, sSQ, scale, nullptr);

    // K3: softmax rows -> bf16 splits
    softmax_split_k<<<8192, 256>>>(s, ah, al);

    // K4: q = a @ vt^T (per batch)
    gemm_mma<<<dim3(16, 16, 4), 256, GEMM_SMEM>>>(
        ah, al, sSQ, vth, vtl, sSQ, q, 2048, sSQ, 1.f, nullptr);

    // gather + split q rows
    gather_split_k<<<dim3(2, 8192, 1), 256>>>(q, qgh, qgl);

    // K5: out = qg @ w_dense^T + bias   M=8192 N=2048 K=2048
    gemm_mma<<<dim3(16, 64, 1), 256, GEMM_SMEM>>>(
        qgh, qgl, 0, wdh, wdl, 0, out, 2048, 0, 1.f, b_dense);
}

// round 6
// speedup vs baseline: 2.4062x; 1.1478x over previous
#include <cuda_runtime.h>
#include <cuda_bf16.h>
#include <math.h>
#include <stdint.h>

// Problem: B=4, T=2048, D=2048, HEADS=16
// Chain:
//   K1: kv = x(8192x2048) @ w_qk^T(4096x2048)      -> g_kv fp32
//   prep: kt=k0^T, v, vt=v^T  (bf16 hi/lo splits, K-major rows of 2048)
//   K2: s[b,i,j] = scale * kt[i,:] . v[j,:]        -> g_s fp32
//   K3: row softmax of s -> bf16 hi/lo splits (a)
//   K4: q = a @ vt^T                                -> g_q fp32
//   prep: qg[r] = q[gather(r)] bf16 splits
//   K5: out = qg @ w_dense^T + bias
//
// GEMM engine: mma.sync m16n8k16 bf16 (plain sm_103 target — tcgen05 is
// 'a'-gated and unavailable). 2-way bf16 split, 3 products (hh, hl, lh).
// R6: 64-deep k stages, 3-stage cp.async ring, ONE __syncthreads per stage.

// ---------------------------------------------------------------- scratch ---
static __device__ float g_kv[33554432];   // 4*2048*4096
static __device__ float g_s [16777216];   // 4*2048*2048
static __device__ float g_q [16777216];   // 4*2048*2048

static __device__ __nv_bfloat16 g_xh[16777216],  g_xl[16777216];
static __device__ __nv_bfloat16 g_wqh[8388608],  g_wql[8388608];
static __device__ __nv_bfloat16 g_wdh[4194304],  g_wdl[4194304];
static __device__ __nv_bfloat16 g_kth[16777216], g_ktl[16777216];
static __device__ __nv_bfloat16 g_vh [16777216], g_vl [16777216];
static __device__ __nv_bfloat16 g_vth[16777216], g_vtl[16777216];
static __device__ __nv_bfloat16 g_ah [16777216], g_al [16777216];
static __device__ __nv_bfloat16 g_qgh[16777216], g_qgl[16777216];

// --------------------------------------------------------------- helpers ---
__device__ __forceinline__ uint32_t smem_u32(const void* p) {
    uint32_t a;
    asm("{ .reg .u64 t; cvta.to.shared.u64 t, %1; cvt.u32.u64 %0, t; }"
        : "=r"(a) : "l"(p));
    return a;
}
__device__ __forceinline__ void cp16(uint32_t dst, const void* src) {
    asm volatile("cp.async.cg.shared.global [%0], [%1], 16;"
                 :: "r"(dst), "l"(src) : "memory");
}
#define CP_COMMIT() asm volatile("cp.async.commit_group;" ::: "memory")
#define CP_WAIT1()  asm volatile("cp.async.wait_group 1;" ::: "memory")

__device__ __forceinline__ void ldsm4(uint32_t* r, uint32_t addr) {
    asm volatile("ldmatrix.sync.aligned.m8n8.x4.shared.b16 {%0,%1,%2,%3}, [%4];"
                 : "=r"(r[0]), "=r"(r[1]), "=r"(r[2]), "=r"(r[3]) : "r"(addr));
}
__device__ __forceinline__ void mma16816(float* c, const uint32_t* a, const uint32_t* b) {
    asm volatile(
        "mma.sync.aligned.m16n8k16.row.col.f32.bf16.bf16.f32 "
        "{%0,%1,%2,%3}, {%4,%5,%6,%7}, {%8,%9}, {%0,%1,%2,%3};"
        : "+f"(c[0]), "+f"(c[1]), "+f"(c[2]), "+f"(c[3])
        : "r"(a[0]), "r"(a[1]), "r"(a[2]), "r"(a[3]), "r"(b[0]), "r"(b[1]));
}

__device__ __forceinline__ void split1(float x, __nv_bfloat16& h, __nv_bfloat16& l) {
    h = __float2bfloat16(x);
    l = __float2bfloat16(x - __bfloat162float(h));
}
__device__ __forceinline__ size_t gather_row_off(int r) {
    int vh = r >> 6;
    int b  = (r >> 4) & 3;
    int h  = r & 15;
    return ((size_t)b * 2048 + (size_t)h * 128 + (size_t)vh) * 2048;
}

// ------------------------------------------------------------ bf16 GEMM ----
// C(m,n) = alpha*sum_k (Ah+Al)(m,k)*(Bh+Bl)(n,k) [+bias(n)], drop Al*Bl.
// Operands K-major bf16, row length 2048, K=2048.
// Block 128x128, k-stage depth 64, 256 thr (8 warps 2x4), warp tile 64x32,
// 3-stage cp.async ring, single __syncthreads per stage iteration.
#define GK       2048
#define GBK      64
#define NCHUNK   (GK / GBK)        // 32
#define ROWB     144u              // 64 bf16 = 128B data + 16B pad
#define TILE_B   (128u * ROWB)     // 18432
#define OFF_AH   0u
#define OFF_AL   TILE_B
#define OFF_BH   (2u * TILE_B)
#define OFF_BL   (3u * TILE_B)
#define STAGE_B  (4u * TILE_B)     // 73728
#define GEMM_SMEM (3u * STAGE_B)   // 221184

__global__ __launch_bounds__(256, 1)
void gemm_mma(const __nv_bfloat16* __restrict__ Ah, const __nv_bfloat16* __restrict__ Al,
              size_t strideA,
              const __nv_bfloat16* __restrict__ Bh, const __nv_bfloat16* __restrict__ Bl,
              size_t strideB,
              float* __restrict__ C, int ldc, size_t strideC,
              float alpha, const float* __restrict__ bias)
{
    extern __shared__ char smem[];
    const uint32_t sbase = smem_u32(smem);

    const int tid  = threadIdx.x;
    const int lane = tid & 31;
    const int wid  = tid >> 5;
    const int wm0  = (wid & 1) * 64;    // warp M offset in tile
    const int wn0  = (wid >> 1) * 32;   // warp N offset in tile

    Ah += blockIdx.z * strideA;  Al += blockIdx.z * strideA;
    Bh += blockIdx.z * strideB;  Bl += blockIdx.z * strideB;
    C  += blockIdx.z * strideC;
    const int m0 = blockIdx.y * 128;
    const int n0 = blockIdx.x * 128;

    // loader: thread -> (row lr + 32*i, 16B chunk lc) per tile
    const int lc = tid & 7;         // chunk 0..7 (8 x 16B per 128B row)
    const int lr = tid >> 3;        // row 0..31

    auto load_stage = [&](int t) {
        if (t < NCHUNK) {
            const uint32_t sb = sbase + (uint32_t)(t % 3) * STAGE_B;
            const int ks = t * GBK;
#pragma unroll
            for (int i = 0; i < 4; i++) {
                const int row = lr + i * 32;
                const uint32_t d = (uint32_t)row * ROWB + lc * 16;
                const size_t aoff = (size_t)(m0 + row) * GK + ks + lc * 8;
                const size_t boff = (size_t)(n0 + row) * GK + ks + lc * 8;
                cp16(sb + OFF_AH + d, Ah + aoff);
                cp16(sb + OFF_AL + d, Al + aoff);
                cp16(sb + OFF_BH + d, Bh + boff);
                cp16(sb + OFF_BL + d, Bl + boff);
            }
        }
        CP_COMMIT();
    };

    float acc[4][4][4];
#pragma unroll
    for (int i = 0; i < 4; i++)
#pragma unroll
        for (int j = 0; j < 4; j++)
#pragma unroll
            for (int k = 0; k < 4; k++) acc[i][j][k] = 0.f;

    // ldmatrix lane-base offsets within a stage
    const uint32_t a_lbase = (uint32_t)(wm0 + (lane & 15)) * ROWB + (uint32_t)(lane >> 4) * 16;
    const uint32_t b_lbase = (uint32_t)(wn0 + ((lane >> 4) & 1) * 8 + (lane & 7)) * ROWB
                           + (uint32_t)((lane >> 3) & 1) * 16;

    load_stage(0);
    load_stage(1);

    for (int t = 0; t < NCHUNK; t++) {
        CP_WAIT1();                 // stage t landed
        __syncthreads();            // also guarantees slot (t-1)%3 is free
        load_stage(t + 2);          // fill slot (t+2)%3 == (t-1)%3

        const uint32_t sb = sbase + (uint32_t)(t % 3) * STAGE_B;
#pragma unroll
        for (int k16 = 0; k16 < 4; k16++) {
            const uint32_t kb = (uint32_t)k16 * 32;   // 16 bf16 = 32 bytes
            uint32_t ah[4][4], al[4][4], bh[2][4], bl[2][4];
#pragma unroll
            for (int mt = 0; mt < 4; mt++) {
                ldsm4(ah[mt], sb + OFF_AH + a_lbase + (uint32_t)mt * (16u * ROWB) + kb);
                ldsm4(al[mt], sb + OFF_AL + a_lbase + (uint32_t)mt * (16u * ROWB) + kb);
            }
#pragma unroll
            for (int p = 0; p < 2; p++) {
                ldsm4(bh[p], sb + OFF_BH + b_lbase + (uint32_t)p * (16u * ROWB) + kb);
                ldsm4(bl[p], sb + OFF_BL + b_lbase + (uint32_t)p * (16u * ROWB) + kb);
            }
#pragma unroll
            for (int mt = 0; mt < 4; mt++) {
#pragma unroll
                for (int p = 0; p < 2; p++) {
                    mma16816(acc[mt][2 * p + 0], ah[mt], &bh[p][0]);
                    mma16816(acc[mt][2 * p + 1], ah[mt], &bh[p][2]);
                    mma16816(acc[mt][2 * p + 0], ah[mt], &bl[p][0]);
                    mma16816(acc[mt][2 * p + 1], ah[mt], &bl[p][2]);
                    mma16816(acc[mt][2 * p + 0], al[mt], &bh[p][0]);
                    mma16816(acc[mt][2 * p + 1], al[mt], &bh[p][2]);
                }
            }
        }
    }

    // ---- epilogue: direct fp32 stores ----
    const int er = lane >> 2;          // row group 0..7
    const int ec = (lane & 3) * 2;     // col pair
#pragma unroll
    for (int mt = 0; mt < 4; mt++) {
#pragma unroll
        for (int nt = 0; nt < 4; nt++) {
            int m = m0 + wm0 + mt * 16 + er;
            int n = n0 + wn0 + nt * 8 + ec;
            float b0 = 0.f, b1 = 0.f;
            if (bias) { b0 = __ldg(bias + n); b1 = __ldg(bias + n + 1); }
            float2 v0, v1;
            v0.x = alpha * acc[mt][nt][0] + b0;
            v0.y = alpha * acc[mt][nt][1] + b1;
            v1.x = alpha * acc[mt][nt][2] + b0;
            v1.y = alpha * acc[mt][nt][3] + b1;
            *(float2*)&C[(size_t)m * (size_t)ldc + n]       = v0;
            *(float2*)&C[(size_t)(m + 8) * (size_t)ldc + n] = v1;
        }
    }
}

// ----------------------------------------------------------- prep kernels ---
__global__ __launch_bounds__(256)
void copy_split_k(const float* __restrict__ src, size_t src_rstride, size_t src_bstride,
                  __nv_bfloat16* __restrict__ dh, __nv_bfloat16* __restrict__ dl,
                  size_t dst_bstride)
{
    size_t row = blockIdx.y;
    size_t col = (size_t)blockIdx.x * 1024 + threadIdx.x * 4;
    float4 v = *(const float4*)(src + (size_t)blockIdx.z * src_bstride + row * src_rstride + col);
    __nv_bfloat16 h0, h1, h2, h3, l0, l1, l2, l3;
    split1(v.x, h0, l0); split1(v.y, h1, l1);
    split1(v.z, h2, l2); split1(v.w, h3, l3);
    size_t o = (size_t)blockIdx.z * dst_bstride + row * 2048 + col;
    ((__nv_bfloat162*)(dh + o))[0] = __halves2bfloat162(h0, h1);
    ((__nv_bfloat162*)(dh + o))[1] = __halves2bfloat162(h2, h3);
    ((__nv_bfloat162*)(dl + o))[0] = __halves2bfloat162(l0, l1);
    ((__nv_bfloat162*)(dl + o))[1] = __halves2bfloat162(l2, l3);
}

__global__ __launch_bounds__(256)
void transpose_split_k(const float* __restrict__ src, size_t src_bstride, int src_ld,
                       __nv_bfloat16* __restrict__ dh, __nv_bfloat16* __restrict__ dl,
                       size_t dst_bstride)
{
    __shared__ float tile[32][33];
    int tx = threadIdx.x, ty = threadIdx.y;      // blockDim (32, 8)
    int i0 = blockIdx.x * 32, m0 = blockIdx.y * 32;
    const float* s = src + (size_t)blockIdx.z * src_bstride;
#pragma unroll
    for (int r = 0; r < 4; r++)
        tile[ty + r * 8][tx] = s[(size_t)(m0 + ty + r * 8) * src_ld + i0 + tx];
    __syncthreads();
#pragma unroll
    for (int r = 0; r < 4; r++) {
        float x = tile[tx][ty + r * 8];
        __nv_bfloat16 h, l; split1(x, h, l);
        size_t o = (size_t)blockIdx.z * dst_bstride +
                   (size_t)(i0 + ty + r * 8) * 2048 + m0 + tx;
        dh[o] = h; dl[o] = l;
    }
}

__global__ __launch_bounds__(256)
void softmax_split_k(const float* __restrict__ s,
                     __nv_bfloat16* __restrict__ ah, __nv_bfloat16* __restrict__ al)
{
    const float* p = s + (size_t)blockIdx.x * 2048;
    int tid = threadIdx.x, warp = tid >> 5, lane = tid & 31;
    __shared__ float red[8];

    float4 v0 = *(const float4*)(p + tid * 4);
    float4 v1 = *(const float4*)(p + 1024 + tid * 4);

    float m = fmaxf(fmaxf(fmaxf(v0.x, v0.y), fmaxf(v0.z, v0.w)),
                    fmaxf(fmaxf(v1.x, v1.y), fmaxf(v1.z, v1.w)));
#pragma unroll
    for (int o = 16; o > 0; o >>= 1) m = fmaxf(m, __shfl_xor_sync(0xffffffffu, m, o));
    if (lane == 0) red[warp] = m;
    __syncthreads();
    float bm = red[0];
#pragma unroll
    for (int i = 1; i < 8; i++) bm = fmaxf(bm, red[i]);
    __syncthreads();

    v0.x = __expf(v0.x - bm); v0.y = __expf(v0.y - bm);
    v0.z = __expf(v0.z - bm); v0.w = __expf(v0.w - bm);
    v1.x = __expf(v1.x - bm); v1.y = __expf(v1.y - bm);
    v1.z = __expf(v1.z - bm); v1.w = __expf(v1.w - bm);

    float sm = v0.x + v0.y + v0.z + v0.w + v1.x + v1.y + v1.z + v1.w;
#pragma unroll
    for (int o = 16; o > 0; o >>= 1) sm += __shfl_xor_sync(0xffffffffu, sm, o);
    if (lane == 0) red[warp] = sm;
    __syncthreads();
    float tot = red[0];
#pragma unroll
    for (int i = 1; i < 8; i++) tot += red[i];
    float inv = 1.f / tot;

    size_t base = (size_t)blockIdx.x * 2048;
    float vals[8] = {v0.x * inv, v0.y * inv, v0.z * inv, v0.w * inv,
                     v1.x * inv, v1.y * inv, v1.z * inv, v1.w * inv};
    size_t offs[2] = {base + tid * 4, base + 1024 + tid * 4};
#pragma unroll
    for (int half = 0; half < 2; half++) {
        __nv_bfloat16 h0, h1, h2, h3, l0, l1, l2, l3;
        split1(vals[half * 4 + 0], h0, l0); split1(vals[half * 4 + 1], h1, l1);
        split1(vals[half * 4 + 2], h2, l2); split1(vals[half * 4 + 3], h3, l3);
        size_t o = offs[half];
        ((__nv_bfloat162*)(ah + o))[0] = __halves2bfloat162(h0, h1);
        ((__nv_bfloat162*)(ah + o))[1] = __halves2bfloat162(h2, h3);
        ((__nv_bfloat162*)(al + o))[0] = __halves2bfloat162(l0, l1);
        ((__nv_bfloat162*)(al + o))[1] = __halves2bfloat162(l2, l3);
    }
}

__global__ __launch_bounds__(256)
void gather_split_k(const float* __restrict__ q,
                    __nv_bfloat16* __restrict__ dh, __nv_bfloat16* __restrict__ dl)
{
    int r = blockIdx.y;
    size_t col = (size_t)blockIdx.x * 1024 + threadIdx.x * 4;
    float4 v = *(const float4*)(q + gather_row_off(r) + col);
    __nv_bfloat16 h0, h1, h2, h3, l0, l1, l2, l3;
    split1(v.x, h0, l0); split1(v.y, h1, l1);
    split1(v.z, h2, l2); split1(v.w, h3, l3);
    size_t o = (size_t)r * 2048 + col;
    ((__nv_bfloat162*)(dh + o))[0] = __halves2bfloat162(h0, h1);
    ((__nv_bfloat162*)(dh + o))[1] = __halves2bfloat162(h2, h3);
    ((__nv_bfloat162*)(dl + o))[0] = __halves2bfloat162(l0, l1);
    ((__nv_bfloat162*)(dl + o))[1] = __halves2bfloat162(l2, l3);
}

// ------------------------------------------------------------------ driver ---
extern "C" void kernel_launch(void* const* d_in, const int* in_sizes, int n_in,
                              void* d_out, int out_size)
{
    const float* x       = (const float*)d_in[0];
    const float* w_qk    = (const float*)d_in[1];
    const float* w_dense = (const float*)d_in[2];
    const float* b_dense = (const float*)d_in[3];
    float* out = (float*)d_out;

    float *kv, *s, *q;
    cudaGetSymbolAddress((void**)&kv, g_kv);
    cudaGetSymbolAddress((void**)&s,  g_s);
    cudaGetSymbolAddress((void**)&q,  g_q);
    __nv_bfloat16 *xh, *xl, *wqh, *wql, *wdh, *wdl, *kth, *ktl, *vh, *vl,
                  *vth, *vtl, *ah, *al, *qgh, *qgl;
    cudaGetSymbolAddress((void**)&xh,  g_xh);  cudaGetSymbolAddress((void**)&xl,  g_xl);
    cudaGetSymbolAddress((void**)&wqh, g_wqh); cudaGetSymbolAddress((void**)&wql, g_wql);
    cudaGetSymbolAddress((void**)&wdh, g_wdh); cudaGetSymbolAddress((void**)&wdl, g_wdl);
    cudaGetSymbolAddress((void**)&kth, g_kth); cudaGetSymbolAddress((void**)&ktl, g_ktl);
    cudaGetSymbolAddress((void**)&vh,  g_vh);  cudaGetSymbolAddress((void**)&vl,  g_vl);
    cudaGetSymbolAddress((void**)&vth, g_vth); cudaGetSymbolAddress((void**)&vtl, g_vtl);
    cudaGetSymbolAddress((void**)&ah,  g_ah);  cudaGetSymbolAddress((void**)&al,  g_al);
    cudaGetSymbolAddress((void**)&qgh, g_qgh); cudaGetSymbolAddress((void**)&qgl, g_qgl);

    cudaFuncSetAttribute(gemm_mma, cudaFuncAttributeMaxDynamicSharedMemorySize, GEMM_SMEM);

    const float scale = (float)(1.0 / sqrt(2048.0 * 2047.0 / 2.0));
    const size_t sKV = 2048ull * 4096ull;
    const size_t sSQ = 2048ull * 2048ull;

    // splits of the raw inputs
    copy_split_k<<<dim3(2, 8192, 1), 256>>>(x,       2048, 0, xh,  xl,  0);
    copy_split_k<<<dim3(2, 4096, 1), 256>>>(w_qk,    2048, 0, wqh, wql, 0);
    copy_split_k<<<dim3(2, 2048, 1), 256>>>(w_dense, 2048, 0, wdh, wdl, 0);

    // K1: kv = x @ w_qk^T   M=8192 N=4096 K=2048
    gemm_mma<<<dim3(32, 64, 1), 256, GEMM_SMEM>>>(
        xh, xl, 0, wqh, wql, 0, kv, 4096, 0, 1.f, nullptr);

    // kv -> kt (k0^T), v (copy), vt (v^T), all bf16 splits
    transpose_split_k<<<dim3(64, 64, 4), dim3(32, 8)>>>(kv,        sKV, 4096, kth, ktl, sSQ);
    copy_split_k     <<<dim3(2, 2048, 4), 256>>>      (kv + 2048, 4096, sKV, vh,  vl,  sSQ);
    transpose_split_k<<<dim3(64, 64, 4), dim3(32, 8)>>>(kv + 2048, sKV, 4096, vth, vtl, sSQ);

    // K2: s = scale * kt @ v^T (per batch)
    gemm_mma<<<dim3(16, 16, 4), 256, GEMM_SMEM>>>(
        kth, ktl, sSQ, vh, vl, sSQ, s, 2048, sSQ, scale, nullptr);

    // K3: softmax rows -> bf16 splits
    softmax_split_k<<<8192, 256>>>(s, ah, al);

    // K4: q = a @ vt^T (per batch)
    gemm_mma<<<dim3(16, 16, 4), 256, GEMM_SMEM>>>(
        ah, al, sSQ, vth, vtl, sSQ, q, 2048, sSQ, 1.f, nullptr);

    // gather + split q rows
    gather_split_k<<<dim3(2, 8192, 1), 256>>>(q, qgh, qgl);

    // K5: out = qg @ w_dense^T + bias   M=8192 N=2048 K=2048
    gemm_mma<<<dim3(16, 64, 1), 256, GEMM_SMEM>>>(
        qgh, qgl, 0, wdh, wdl, 0, out, 2048, 0, 1.f, b_dense);
}